// round 15
// baseline (speedup 1.0000x reference)
#include <cuda_runtime.h>
#include <cuda_bf16.h>
#include <cstdint>
#include <math.h>

#define LSEQ     2048
#define HIDDEN   2048
#define INTER    4096
#define HEADS    64
#define HEAD_DIM 64
#define STATE    64
#define KCONV    4
#define CONV_DIM (INTER + 2 * STATE)            // 4224
#define PROJ     (INTER + CONV_DIM + HEADS)     // 8384
#define W1_RPAD  8448                           // PROJ padded to 128
#define NSEG     4
#define SEGL     (LSEQ / NSEG)                  // 512

// ---------------- scratch ------------------------------------------------
__device__ float g_proj[(size_t)LSEQ * PROJ];
__device__ float g_conv[(size_t)LSEQ * CONV_DIM];
__device__ float g_y[(size_t)LSEQ * INTER];      // scan partial (n 0..31) + correction
__device__ float g_y2[(size_t)LSEQ * INTER];     // scan partial (n 32..63)
__device__ float g_dtv[LSEQ * HEADS];
__device__ float g_dA[LSEQ * HEADS];
__device__ float g_cum[(size_t)LSEQ * HEADS];    // intra-segment cumulative decay [t][h]
__device__ float g_send[(size_t)NSEG * HEADS * 64 * 64];  // segment-exit local state
__device__ float g_sin[(size_t)NSEG * HEADS * 64 * 64];   // true segment-entry state
// bf16 split operands (u32 = packed bf16 pair, k-permuted layout)
__device__ uint32_t g_h_hi[(size_t)LSEQ * (HIDDEN / 2)];
__device__ uint32_t g_h_lo[(size_t)LSEQ * (HIDDEN / 2)];
__device__ uint32_t g_w1_hi[(size_t)W1_RPAD * (HIDDEN / 2)];
__device__ uint32_t g_w1_lo[(size_t)W1_RPAD * (HIDDEN / 2)];
__device__ uint32_t g_w2_hi[(size_t)HIDDEN * (INTER / 2)];
__device__ uint32_t g_w2_lo[(size_t)HIDDEN * (INTER / 2)];
__device__ uint32_t g_yn_hi[(size_t)LSEQ * (INTER / 2)];
__device__ uint32_t g_yn_lo[(size_t)LSEQ * (INTER / 2)];

// ---------------- helpers --------------------------------------------------
__device__ __forceinline__ void split_pack(float x0, float x1, uint32_t& hi, uint32_t& lo) {
    __nv_bfloat16 h0 = __float2bfloat16(x0);
    __nv_bfloat16 h1 = __float2bfloat16(x1);
    __nv_bfloat16 l0 = __float2bfloat16(x0 - __bfloat162float(h0));
    __nv_bfloat16 l1 = __float2bfloat16(x1 - __bfloat162float(h1));
    hi = (uint32_t)__bfloat16_as_ushort(h0) | ((uint32_t)__bfloat16_as_ushort(h1) << 16);
    lo = (uint32_t)__bfloat16_as_ushort(l0) | ((uint32_t)__bfloat16_as_ushort(l1) << 16);
}

__device__ __forceinline__ void mma_bf16(float* d, const uint32_t* a, const uint32_t* b) {
    asm volatile(
        "mma.sync.aligned.m16n8k16.row.col.f32.bf16.bf16.f32 "
        "{%0,%1,%2,%3}, {%4,%5,%6,%7}, {%8,%9}, {%0,%1,%2,%3};"
        : "+f"(d[0]), "+f"(d[1]), "+f"(d[2]), "+f"(d[3])
        : "r"(a[0]), "r"(a[1]), "r"(a[2]), "r"(a[3]), "r"(b[0]), "r"(b[1]));
}

__device__ __forceinline__ uint32_t smem_u32p(const void* p) {
    uint32_t a;
    asm("{ .reg .u64 t; cvta.to.shared.u64 t, %1; cvt.u32.u64 %0, t; }" : "=r"(a) : "l"(p));
    return a;
}
__device__ __forceinline__ void cp16(uint32_t dst, const void* src) {
    asm volatile("cp.async.cg.shared.global [%0], [%1], 16;" :: "r"(dst), "l"(src));
}
__device__ __forceinline__ void cp_commit() { asm volatile("cp.async.commit_group;"); }
__device__ __forceinline__ void cp_wait1()  { asm volatile("cp.async.wait_group 1;" ::: "memory"); }
__device__ __forceinline__ void cp_wait0()  { asm volatile("cp.async.wait_group 0;" ::: "memory"); }

// ---------------- convert f32 -> permuted bf16 hi/lo pairs (R5 layout) -----
__global__ void cvt_split(const float* __restrict__ in, uint32_t* __restrict__ hi,
                          uint32_t* __restrict__ lo, int R, int K)
{
    const int K2 = K >> 1;
    int jj  = blockIdx.x * blockDim.x + threadIdx.x;
    int row = blockIdx.y;
    if (jj >= K2) return;
    int g = jj >> 3, p = jj & 7;
    int jl = (g << 3) + (p >> 1) + ((p & 1) << 2);
    float a0 = 0.f, a1 = 0.f;
    if (row < R) {
        a0 = in[(size_t)row * K + 2 * jl];
        a1 = in[(size_t)row * K + 2 * jl + 1];
    }
    uint32_t h, l;
    split_pack(a0, a1, h, l);
    hi[(size_t)row * K2 + jj] = h;
    lo[(size_t)row * K2 + jj] = l;
}

// ---------------- bf16x3 GEMM (R10 measured best, unchanged) ----------------
#define BM 128
#define BN 128
#define BKE 32
#define BUF_U32 (BM * 16)              // 2048
#define STAGE_U32 (4 * BUF_U32)        // 8192
#define GEMM_SMEM_BYTES (3 * STAGE_U32 * 4)   // 98304

__global__ __launch_bounds__(256, 2) void gemm_bf3(
    const uint32_t* __restrict__ Ahi, const uint32_t* __restrict__ Alo,
    const uint32_t* __restrict__ Bhi, const uint32_t* __restrict__ Blo,
    float* __restrict__ C, int M, int N, int K)
{
    extern __shared__ uint32_t dsm[];
    const int K2  = K >> 1;
    const int nst = K / BKE;
    const int tid  = threadIdx.x;
    const int wid  = tid >> 5;
    const int lane = tid & 31;
    const int wm   = wid & 1;
    const int wn   = wid >> 1;
    const int m0   = blockIdx.y * BM;
    const int n0   = blockIdx.x * BN;
    const int lg   = lane >> 2;
    const int lc   = lane & 3;

    const uint32_t sbase = smem_u32p(dsm);
    const int crow = tid >> 1;
    const int cj   = (tid & 1) * 2;
    const int rsw  = (crow >> 1) & 1;

    float acc[4][4][4];
#pragma unroll
    for (int i = 0; i < 4; ++i)
#pragma unroll
        for (int j = 0; j < 4; ++j)
#pragma unroll
            for (int q = 0; q < 4; ++q) acc[i][j][q] = 0.f;

    auto issue = [&](int s) {
        const uint32_t st = sbase + ((s % 3) * STAGE_U32) * 4;
        const size_t ga = (size_t)(m0 + crow) * K2 + (size_t)s * 16;
        const size_t gb = (size_t)(n0 + crow) * K2 + (size_t)s * 16;
#pragma unroll
        for (int c = 0; c < 2; ++c) {
            const int j  = cj + (c ^ rsw);
            const int jp = j ^ (crow & 3);
            const uint32_t d = st + (crow * 16 + jp * 4) * 4;
            cp16(d,                    Ahi + ga + j * 4);
            cp16(d + BUF_U32 * 4,      Alo + ga + j * 4);
            cp16(d + 2 * BUF_U32 * 4,  Bhi + gb + j * 4);
            cp16(d + 3 * BUF_U32 * 4,  Blo + gb + j * 4);
        }
    };

    issue(0); cp_commit();
    issue(1); cp_commit();

    for (int s = 0; s < nst; ++s) {
        if (s < nst - 1) cp_wait1(); else cp_wait0();
        __syncthreads();
        if (s + 2 < nst) { issue(s + 2); cp_commit(); }

        const uint32_t* st   = dsm + (s % 3) * STAGE_U32;
        const uint32_t* pAhi = st;
        const uint32_t* pAlo = st + BUF_U32;
        const uint32_t* pBhi = st + 2 * BUF_U32;
        const uint32_t* pBlo = st + 3 * BUF_U32;

#pragma unroll
        for (int ks = 0; ks < 2; ++ks) {
            const int jw = ks * 8 + 2 * lc;
            uint2 aH0[4], aH1[4], aL0[4], aL1[4], bH[4], bL[4];
#pragma unroll
            for (int mt = 0; mt < 4; ++mt) {
                int r0 = wm * 64 + mt * 16 + lg;
                int sx = (r0 & 3) << 2;
                int o0 = r0 * 16 + (jw ^ sx);
                int o1 = (r0 + 8) * 16 + (jw ^ sx);
                aH0[mt] = *reinterpret_cast<const uint2*>(pAhi + o0);
                aH1[mt] = *reinterpret_cast<const uint2*>(pAhi + o1);
                aL0[mt] = *reinterpret_cast<const uint2*>(pAlo + o0);
                aL1[mt] = *reinterpret_cast<const uint2*>(pAlo + o1);
            }
#pragma unroll
            for (int nt = 0; nt < 4; ++nt) {
                int rb = wn * 32 + nt * 8 + lg;
                int ob = rb * 16 + (jw ^ ((rb & 3) << 2));
                bH[nt] = *reinterpret_cast<const uint2*>(pBhi + ob);
                bL[nt] = *reinterpret_cast<const uint2*>(pBlo + ob);
            }
#pragma unroll
            for (int mt = 0; mt < 4; ++mt) {
                uint32_t ah[4] = {aH0[mt].x, aH1[mt].x, aH0[mt].y, aH1[mt].y};
#pragma unroll
                for (int nt = 0; nt < 4; ++nt) {
                    uint32_t bh[2] = {bH[nt].x, bH[nt].y};
                    mma_bf16(acc[mt][nt], ah, bh);
                }
            }
#pragma unroll
            for (int mt = 0; mt < 4; ++mt) {
                uint32_t ah[4] = {aH0[mt].x, aH1[mt].x, aH0[mt].y, aH1[mt].y};
#pragma unroll
                for (int nt = 0; nt < 4; ++nt) {
                    uint32_t bl[2] = {bL[nt].x, bL[nt].y};
                    mma_bf16(acc[mt][nt], ah, bl);
                }
            }
#pragma unroll
            for (int mt = 0; mt < 4; ++mt) {
                uint32_t al[4] = {aL0[mt].x, aL1[mt].x, aL0[mt].y, aL1[mt].y};
#pragma unroll
                for (int nt = 0; nt < 4; ++nt) {
                    uint32_t bh[2] = {bH[nt].x, bH[nt].y};
                    mma_bf16(acc[mt][nt], al, bh);
                }
            }
        }
    }

#pragma unroll
    for (int mt = 0; mt < 4; ++mt) {
        int r0 = m0 + wm * 64 + mt * 16 + lg;
#pragma unroll
        for (int nt = 0; nt < 4; ++nt) {
            int gc = n0 + wn * 32 + nt * 8 + lc * 2;
            if (gc < N) {
                *reinterpret_cast<float2*>(&C[(size_t)r0 * N + gc]) =
                    make_float2(acc[mt][nt][0], acc[mt][nt][1]);
                *reinterpret_cast<float2*>(&C[(size_t)(r0 + 8) * N + gc]) =
                    make_float2(acc[mt][nt][2], acc[mt][nt][3]);
            }
        }
    }
}

// ---------------- fused conv+silu and dt transform --------------------------
__global__ void conv_dt_kernel(const float* __restrict__ conv_w,
                               const float* __restrict__ conv_b,
                               const float* __restrict__ dt_bias,
                               const float* __restrict__ A_log)
{
    int idx = blockIdx.x * blockDim.x + threadIdx.x;
    if (idx < LSEQ * CONV_DIM) {
        int c = idx % CONV_DIM;
        int t = idx / CONV_DIM;
        const float4 w = *reinterpret_cast<const float4*>(&conv_w[c * 4]);
        const float* col = g_proj + INTER + c;
        float acc = conv_b[c];
        if (t - 3 >= 0) acc = fmaf(col[(size_t)(t - 3) * PROJ], w.x, acc);
        if (t - 2 >= 0) acc = fmaf(col[(size_t)(t - 2) * PROJ], w.y, acc);
        if (t - 1 >= 0) acc = fmaf(col[(size_t)(t - 1) * PROJ], w.z, acc);
        acc = fmaf(col[(size_t)t * PROJ], w.w, acc);
        g_conv[idx] = acc / (1.f + expf(-acc));
    } else {
        int j = idx - LSEQ * CONV_DIM;
        if (j >= LSEQ * HEADS) return;
        int h = j & (HEADS - 1);
        int t = j >> 6;
        float z = g_proj[(size_t)t * PROJ + INTER + CONV_DIM + h] + dt_bias[h];
        float d = (z > 20.f) ? z : log1pf(expf(z));
        float A = -expf(A_log[h]);
        g_dtv[j] = d;
        g_dA[j]  = expf(d * A);
    }
}

// ---------------- segmented selective scan (v3 body, 4 segments) ------------
#define TCH 8
#define SCH (SEGL / TCH)     // 64 chunks per segment
__global__ __launch_bounds__(128) void scan_kernel(const float* __restrict__ D)
{
    const int h   = blockIdx.x >> 2;
    const int ph  = (blockIdx.x >> 1) & 1;
    const int nh  = blockIdx.x & 1;
    const int seg = blockIdx.y;
    const int T0  = seg * SEGL;
    const int tid = threadIdx.x;
    const int pl  = tid >> 2;
    const int q   = tid & 3;
    const int n0  = q * 8;
    const float Dh = D[h];
    float* yout = nh ? g_y2 : g_y;
    const bool cw = (ph == 0 && nh == 0 && tid == 0);

    __shared__ float sB[2][TCH][32], sC[2][TCH][32], sX[2][TCH][32];
    __shared__ float sDT[2][TCH], sDA[2][TCH];

    const int tl   = tid >> 4;
    const int col2 = tid & 15;

    {
        const float* rowp = g_conv + (size_t)(T0 + tl) * CONV_DIM;
        *reinterpret_cast<float2*>(&sB[0][tl][col2 * 2]) =
            *reinterpret_cast<const float2*>(&rowp[INTER + nh * 32 + col2 * 2]);
        *reinterpret_cast<float2*>(&sC[0][tl][col2 * 2]) =
            *reinterpret_cast<const float2*>(&rowp[INTER + STATE + nh * 32 + col2 * 2]);
        *reinterpret_cast<float2*>(&sX[0][tl][col2 * 2]) =
            *reinterpret_cast<const float2*>(&rowp[h * HEAD_DIM + ph * 32 + col2 * 2]);
        if (tid < TCH)           sDT[0][tid]       = g_dtv[(T0 + tid) * HEADS + h];
        else if (tid < 2 * TCH)  sDA[0][tid - TCH] = g_dA[(T0 + tid - TCH) * HEADS + h];
    }
    __syncthreads();

    float s[8];
#pragma unroll
    for (int i = 0; i < 8; ++i) s[i] = 0.f;
    float cum = 1.f;

    for (int c = 0; c < SCH; ++c) {
        const int buf = c & 1;
        const int t0  = T0 + c * TCH;
        const bool more = (c + 1 < SCH);

        float2 nB, nC, nX; float nS = 0.f;
        if (more) {
            const float* rowp = g_conv + (size_t)(t0 + TCH + tl) * CONV_DIM;
            nB = *reinterpret_cast<const float2*>(&rowp[INTER + nh * 32 + col2 * 2]);
            nC = *reinterpret_cast<const float2*>(&rowp[INTER + STATE + nh * 32 + col2 * 2]);
            nX = *reinterpret_cast<const float2*>(&rowp[h * HEAD_DIM + ph * 32 + col2 * 2]);
            if (tid < TCH)           nS = g_dtv[(t0 + TCH + tid) * HEADS + h];
            else if (tid < 2 * TCH)  nS = g_dA[(t0 + TCH + tid - TCH) * HEADS + h];
        }

#pragma unroll
        for (int k = 0; k < TCH; ++k) {
            const float a   = sDA[buf][k];
            const float dtv = sDT[buf][k];
            const float xv  = sX[buf][k][pl];
            const float dtx = dtv * xv;
            float4 b0 = *reinterpret_cast<const float4*>(&sB[buf][k][n0]);
            float4 b1 = *reinterpret_cast<const float4*>(&sB[buf][k][n0 + 4]);
            float4 c0 = *reinterpret_cast<const float4*>(&sC[buf][k][n0]);
            float4 c1 = *reinterpret_cast<const float4*>(&sC[buf][k][n0 + 4]);
            s[0] = fmaf(a, s[0], dtx * b0.x);
            s[1] = fmaf(a, s[1], dtx * b0.y);
            s[2] = fmaf(a, s[2], dtx * b0.z);
            s[3] = fmaf(a, s[3], dtx * b0.w);
            s[4] = fmaf(a, s[4], dtx * b1.x);
            s[5] = fmaf(a, s[5], dtx * b1.y);
            s[6] = fmaf(a, s[6], dtx * b1.z);
            s[7] = fmaf(a, s[7], dtx * b1.w);
            float e0 = fmaf(s[1], c0.y, s[0] * c0.x);
            float e1 = fmaf(s[3], c0.w, s[2] * c0.z);
            float e2 = fmaf(s[5], c1.y, s[4] * c1.x);
            float e3 = fmaf(s[7], c1.w, s[6] * c1.z);
            float accv = (e0 + e1) + (e2 + e3);
            accv += __shfl_xor_sync(0xffffffffu, accv, 1);
            accv += __shfl_xor_sync(0xffffffffu, accv, 2);
            cum *= a;
            if (cw) g_cum[(size_t)(t0 + k) * HEADS + h] = cum;
            if (q == 0) {
                float o = accv + (nh == 0 ? Dh * xv : 0.f);
                yout[(size_t)(t0 + k) * INTER + h * HEAD_DIM + ph * 32 + pl] = o;
            }
        }

        if (more) {
            const int nb = buf ^ 1;
            *reinterpret_cast<float2*>(&sB[nb][tl][col2 * 2]) = nB;
            *reinterpret_cast<float2*>(&sC[nb][tl][col2 * 2]) = nC;
            *reinterpret_cast<float2*>(&sX[nb][tl][col2 * 2]) = nX;
            if (tid < TCH)           sDT[nb][tid]       = nS;
            else if (tid < 2 * TCH)  sDA[nb][tid - TCH] = nS;
        }
        __syncthreads();
    }

    // segment-exit local state
    {
        size_t sb = ((((size_t)seg * HEADS) + h) * 64 + (ph * 32 + pl)) * 64 + nh * 32 + n0;
        *reinterpret_cast<float4*>(&g_send[sb])     = make_float4(s[0], s[1], s[2], s[3]);
        *reinterpret_cast<float4*>(&g_send[sb + 4]) = make_float4(s[4], s[5], s[6], s[7]);
    }
}

// ---------------- boundary-state propagation ---------------------------------
__global__ __launch_bounds__(256) void prop_kernel()
{
    int idx = blockIdx.x * 256 + threadIdx.x;      // 65536 = 64h * 64p * 16n4
    int h  = idx >> 10;
    int rem = idx & 1023;
    int p  = rem >> 4;
    int n4 = (rem & 15) * 4;
    float4 s = make_float4(0.f, 0.f, 0.f, 0.f);
    for (int k = 1; k < NSEG; ++k) {
        float Dk = g_cum[((size_t)k * SEGL - 1) * HEADS + h];
        const float4 e = *reinterpret_cast<const float4*>(
            &g_send[(((size_t)(k - 1) * HEADS + h) * 64 + p) * 64 + n4]);
        s.x = fmaf(Dk, s.x, e.x);
        s.y = fmaf(Dk, s.y, e.y);
        s.z = fmaf(Dk, s.z, e.z);
        s.w = fmaf(Dk, s.w, e.w);
        *reinterpret_cast<float4*>(
            &g_sin[(((size_t)k * HEADS + h) * 64 + p) * 64 + n4]) = s;
    }
}

// ---------------- correction: y_t += cumdA_t * (C_t . s_in) -------------------
__global__ __launch_bounds__(256) void corr_kernel()
{
    const int h   = blockIdx.y;
    const int seg = blockIdx.x + 1;
    const int T0  = seg * SEGL;
    const int tid = threadIdx.x;
    const int p   = tid >> 2;
    const int nq  = tid & 3;
    const int n0  = nq * 16;

    // this thread's 16-state slice of s_in, in registers
    const float* sp = g_sin + (((size_t)seg * HEADS + h) * 64 + p) * 64 + n0;
    float4 sr0 = *reinterpret_cast<const float4*>(sp);
    float4 sr1 = *reinterpret_cast<const float4*>(sp + 4);
    float4 sr2 = *reinterpret_cast<const float4*>(sp + 8);
    float4 sr3 = *reinterpret_cast<const float4*>(sp + 12);

    __shared__ float sC[2][TCH][64];
    __shared__ float sCum[2][TCH];

    auto loadstage = [&](int buf, int cb) {
        int t = T0 + cb * TCH;
        if (tid < 128) {
            int tl = tid >> 4, c4 = (tid & 15) * 4;
            *reinterpret_cast<float4*>(&sC[buf][tl][c4]) =
                *reinterpret_cast<const float4*>(
                    &g_conv[(size_t)(t + tl) * CONV_DIM + INTER + STATE + c4]);
        } else if (tid < 128 + TCH) {
            sCum[buf][tid - 128] = g_cum[(size_t)(t + tid - 128) * HEADS + h];
        }
    };

    loadstage(0, 0);
    __syncthreads();

    for (int cb = 0; cb < SCH; ++cb) {
        const int buf = cb & 1;
        if (cb + 1 < SCH) loadstage(buf ^ 1, cb + 1);
#pragma unroll
        for (int k = 0; k < TCH; ++k) {
            float4 c0 = *reinterpret_cast<const float4*>(&sC[buf][k][n0]);
            float4 c1 = *reinterpret_cast<const float4*>(&sC[buf][k][n0 + 4]);
            float4 c2 = *reinterpret_cast<const float4*>(&sC[buf][k][n0 + 8]);
            float4 c3 = *reinterpret_cast<const float4*>(&sC[buf][k][n0 + 12]);
            float a0 = fmaf(c0.y, sr0.y, c0.x * sr0.x);
            a0 = fmaf(c0.z, sr0.z, a0); a0 = fmaf(c0.w, sr0.w, a0);
            float a1 = fmaf(c1.y, sr1.y, c1.x * sr1.x);
            a1 = fmaf(c1.z, sr1.z, a1); a1 = fmaf(c1.w, sr1.w, a1);
            float a2 = fmaf(c2.y, sr2.y, c2.x * sr2.x);
            a2 = fmaf(c2.z, sr2.z, a2); a2 = fmaf(c2.w, sr2.w, a2);
            float a3 = fmaf(c3.y, sr3.y, c3.x * sr3.x);
            a3 = fmaf(c3.z, sr3.z, a3); a3 = fmaf(c3.w, sr3.w, a3);
            float acc = (a0 + a1) + (a2 + a3);
            acc += __shfl_xor_sync(0xffffffffu, acc, 1);
            acc += __shfl_xor_sync(0xffffffffu, acc, 2);
            if (nq == 0) {
                size_t yi = (size_t)(T0 + cb * TCH + k) * INTER + h * HEAD_DIM + p;
                g_y[yi] += sCum[buf][k] * acc;
            }
        }
        __syncthreads();
    }
}

// ---------------- RMSNorm * silu(gate) -> bf16 hi/lo (R5 permutation) ---------
__global__ __launch_bounds__(256) void norm_gate_cvt(const float* __restrict__ nw)
{
    const int t = blockIdx.x;
    const float* y1 = g_y  + (size_t)t * INTER;
    const float* y2 = g_y2 + (size_t)t * INTER;
    const float* gp = g_proj + (size_t)t * PROJ;
    __shared__ float red[256];
    float ss = 0.f;
    for (int c = threadIdx.x; c < INTER; c += 256) {
        float v = y1[c] + y2[c];
        ss = fmaf(v, v, ss);
    }
    red[threadIdx.x] = ss;
    __syncthreads();
    for (int off = 128; off > 0; off >>= 1) {
        if (threadIdx.x < off) red[threadIdx.x] += red[threadIdx.x + off];
        __syncthreads();
    }
    const float r = rsqrtf(red[0] / (float)INTER + 1e-6f);

    const int K2 = INTER / 2;
    for (int J = threadIdx.x; J < K2; J += 256) {
        int g = J >> 3, p = J & 7;
        int jl = (g << 3) + (p >> 1) + ((p & 1) << 2);
        int c0 = 2 * jl;
        float ga = gp[c0], gb = gp[c0 + 1];
        float v0 = (y1[c0] + y2[c0]) * r * nw[c0] * (ga / (1.f + expf(-ga)));
        float v1 = (y1[c0 + 1] + y2[c0 + 1]) * r * nw[c0 + 1] * (gb / (1.f + expf(-gb)));
        uint32_t h, l;
        split_pack(v0, v1, h, l);
        g_yn_hi[(size_t)t * K2 + J] = h;
        g_yn_lo[(size_t)t * K2 + J] = l;
    }
}

// ---------------- launch ------------------------------------------------------
extern "C" void kernel_launch(void* const* d_in, const int* in_sizes, int n_in,
                              void* d_out, int out_size)
{
    const float* hidden     = (const float*)d_in[0];
    const float* in_proj_w  = (const float*)d_in[1];
    const float* conv_w     = (const float*)d_in[2];
    const float* conv_b     = (const float*)d_in[3];
    const float* dt_bias    = (const float*)d_in[4];
    const float* A_log      = (const float*)d_in[5];
    const float* Dv         = (const float*)d_in[6];
    const float* norm_w     = (const float*)d_in[7];
    const float* out_proj_w = (const float*)d_in[8];
    float* out = (float*)d_out;

    float* p_proj = nullptr;
    cudaGetSymbolAddress((void**)&p_proj, g_proj);
    uint32_t *p_hhi, *p_hlo, *p_w1hi, *p_w1lo, *p_w2hi, *p_w2lo, *p_ynhi, *p_ynlo;
    cudaGetSymbolAddress((void**)&p_hhi, g_h_hi);
    cudaGetSymbolAddress((void**)&p_hlo, g_h_lo);
    cudaGetSymbolAddress((void**)&p_w1hi, g_w1_hi);
    cudaGetSymbolAddress((void**)&p_w1lo, g_w1_lo);
    cudaGetSymbolAddress((void**)&p_w2hi, g_w2_hi);
    cudaGetSymbolAddress((void**)&p_w2lo, g_w2_lo);
    cudaGetSymbolAddress((void**)&p_ynhi, g_yn_hi);
    cudaGetSymbolAddress((void**)&p_ynlo, g_yn_lo);

    cudaFuncSetAttribute(gemm_bf3, cudaFuncAttributeMaxDynamicSharedMemorySize, GEMM_SMEM_BYTES);

    // operand converts needed before GEMM1
    cvt_split<<<dim3(HIDDEN / 2 / 256, LSEQ), 256>>>(hidden, p_hhi, p_hlo, LSEQ, HIDDEN);
    cvt_split<<<dim3(HIDDEN / 2 / 256, W1_RPAD), 256>>>(in_proj_w, p_w1hi, p_w1lo, PROJ, HIDDEN);

    // GEMM1: proj = hidden @ in_proj_w^T : M=2048, N=8384 (pad 8448), K=2048
    gemm_bf3<<<dim3(W1_RPAD / BN, LSEQ / BM), 256, GEMM_SMEM_BYTES>>>(
        p_hhi, p_hlo, p_w1hi, p_w1lo, p_proj, LSEQ, PROJ, HIDDEN);

    // fork: w2 conversion overlaps with latency-bound scan branch (R14 pattern)
    cudaStream_t s1;
    cudaStreamCreateWithFlags(&s1, cudaStreamNonBlocking);
    cudaEvent_t evA, evB;
    cudaEventCreateWithFlags(&evA, cudaEventDisableTiming);
    cudaEventCreateWithFlags(&evB, cudaEventDisableTiming);

    cudaEventRecord(evA, 0);
    cudaStreamWaitEvent(s1, evA, 0);
    cvt_split<<<dim3(INTER / 2 / 256, HIDDEN), 256, 0, s1>>>(out_proj_w, p_w2hi, p_w2lo, HIDDEN, INTER);
    cudaEventRecord(evB, s1);

    // scan branch (legacy stream)
    {
        int total = LSEQ * (CONV_DIM + HEADS);
        conv_dt_kernel<<<(total + 255) / 256, 256>>>(conv_w, conv_b, dt_bias, A_log);
    }
    scan_kernel<<<dim3(HEADS * 4, NSEG), 128>>>(Dv);
    prop_kernel<<<256, 256>>>();
    corr_kernel<<<dim3(NSEG - 1, HEADS), 256>>>();
    norm_gate_cvt<<<LSEQ, 256>>>(norm_w);

    // join before GEMM2 (needs w2 converts + yn)
    cudaStreamWaitEvent(0, evB, 0);

    // GEMM2: out = y' @ out_proj_w^T : M=2048, N=2048, K=4096
    gemm_bf3<<<dim3(HIDDEN / BN, LSEQ / BM), 256, GEMM_SMEM_BYTES>>>(
        p_ynhi, p_ynlo, p_w2hi, p_w2lo, out, LSEQ, HIDDEN, INTER);

    cudaEventDestroy(evA);
    cudaEventDestroy(evB);
    cudaStreamDestroy(s1);
}

// round 16
// speedup vs baseline: 1.0575x; 1.0575x over previous
#include <cuda_runtime.h>
#include <cuda_bf16.h>
#include <cstdint>
#include <math.h>

#define LSEQ     2048
#define HIDDEN   2048
#define INTER    4096
#define HEADS    64
#define HEAD_DIM 64
#define STATE    64
#define KCONV    4
#define CONV_DIM (INTER + 2 * STATE)            // 4224
#define PROJ     (INTER + CONV_DIM + HEADS)     // 8384
#define W1_RPAD  8448                           // PROJ padded to 128

// ---------------- scratch ------------------------------------------------
__device__ float g_proj[(size_t)LSEQ * PROJ];
__device__ float g_conv[(size_t)LSEQ * CONV_DIM];
__device__ float g_y[(size_t)LSEQ * INTER];      // scan partial (n 0..31)
__device__ float g_y2[(size_t)LSEQ * INTER];     // scan partial (n 32..63)
__device__ float g_dtv[LSEQ * HEADS];
__device__ float g_dA[LSEQ * HEADS];
// bf16 split operands (u32 = packed bf16 pair, k-permuted layout)
__device__ uint32_t g_h_hi[(size_t)LSEQ * (HIDDEN / 2)];
__device__ uint32_t g_h_lo[(size_t)LSEQ * (HIDDEN / 2)];
__device__ uint32_t g_w1_hi[(size_t)W1_RPAD * (HIDDEN / 2)];
__device__ uint32_t g_w1_lo[(size_t)W1_RPAD * (HIDDEN / 2)];
__device__ uint32_t g_w2_hi[(size_t)HIDDEN * (INTER / 2)];
__device__ uint32_t g_w2_lo[(size_t)HIDDEN * (INTER / 2)];
__device__ uint32_t g_yn_hi[(size_t)LSEQ * (INTER / 2)];
__device__ uint32_t g_yn_lo[(size_t)LSEQ * (INTER / 2)];

// ---------------- helpers --------------------------------------------------
__device__ __forceinline__ float fast_silu(float x) {
    return __fdividef(x, 1.f + __expf(-x));
}

__device__ __forceinline__ void split_pack(float x0, float x1, uint32_t& hi, uint32_t& lo) {
    __nv_bfloat16 h0 = __float2bfloat16(x0);
    __nv_bfloat16 h1 = __float2bfloat16(x1);
    __nv_bfloat16 l0 = __float2bfloat16(x0 - __bfloat162float(h0));
    __nv_bfloat16 l1 = __float2bfloat16(x1 - __bfloat162float(h1));
    hi = (uint32_t)__bfloat16_as_ushort(h0) | ((uint32_t)__bfloat16_as_ushort(h1) << 16);
    lo = (uint32_t)__bfloat16_as_ushort(l0) | ((uint32_t)__bfloat16_as_ushort(l1) << 16);
}

__device__ __forceinline__ void mma_bf16(float* d, const uint32_t* a, const uint32_t* b) {
    asm volatile(
        "mma.sync.aligned.m16n8k16.row.col.f32.bf16.bf16.f32 "
        "{%0,%1,%2,%3}, {%4,%5,%6,%7}, {%8,%9}, {%0,%1,%2,%3};"
        : "+f"(d[0]), "+f"(d[1]), "+f"(d[2]), "+f"(d[3])
        : "r"(a[0]), "r"(a[1]), "r"(a[2]), "r"(a[3]), "r"(b[0]), "r"(b[1]));
}

__device__ __forceinline__ uint32_t smem_u32p(const void* p) {
    uint32_t a;
    asm("{ .reg .u64 t; cvta.to.shared.u64 t, %1; cvt.u32.u64 %0, t; }" : "=r"(a) : "l"(p));
    return a;
}
__device__ __forceinline__ void cp16(uint32_t dst, const void* src) {
    asm volatile("cp.async.cg.shared.global [%0], [%1], 16;" :: "r"(dst), "l"(src));
}
__device__ __forceinline__ void cp_commit() { asm volatile("cp.async.commit_group;"); }
__device__ __forceinline__ void cp_wait1()  { asm volatile("cp.async.wait_group 1;" ::: "memory"); }
__device__ __forceinline__ void cp_wait0()  { asm volatile("cp.async.wait_group 0;" ::: "memory"); }

// ---------------- convert f32 -> permuted bf16 hi/lo pairs (R5 layout) -----
__global__ void cvt_split(const float* __restrict__ in, uint32_t* __restrict__ hi,
                          uint32_t* __restrict__ lo, int R, int K)
{
    const int K2 = K >> 1;
    int jj  = blockIdx.x * blockDim.x + threadIdx.x;
    int row = blockIdx.y;
    if (jj >= K2) return;
    int g = jj >> 3, p = jj & 7;
    int jl = (g << 3) + (p >> 1) + ((p & 1) << 2);
    float a0 = 0.f, a1 = 0.f;
    if (row < R) {
        a0 = in[(size_t)row * K + 2 * jl];
        a1 = in[(size_t)row * K + 2 * jl + 1];
    }
    uint32_t h, l;
    split_pack(a0, a1, h, l);
    hi[(size_t)row * K2 + jj] = h;
    lo[(size_t)row * K2 + jj] = l;
}

// ---------------- bf16x3 GEMM (R10 measured best, unchanged) ----------------
#define BM 128
#define BN 128
#define BKE 32
#define BUF_U32 (BM * 16)              // 2048
#define STAGE_U32 (4 * BUF_U32)        // 8192
#define GEMM_SMEM_BYTES (3 * STAGE_U32 * 4)   // 98304

__global__ __launch_bounds__(256, 2) void gemm_bf3(
    const uint32_t* __restrict__ Ahi, const uint32_t* __restrict__ Alo,
    const uint32_t* __restrict__ Bhi, const uint32_t* __restrict__ Blo,
    float* __restrict__ C, int M, int N, int K)
{
    extern __shared__ uint32_t dsm[];
    const int K2  = K >> 1;
    const int nst = K / BKE;
    const int tid  = threadIdx.x;
    const int wid  = tid >> 5;
    const int lane = tid & 31;
    const int wm   = wid & 1;
    const int wn   = wid >> 1;
    const int m0   = blockIdx.y * BM;
    const int n0   = blockIdx.x * BN;
    const int lg   = lane >> 2;
    const int lc   = lane & 3;

    const uint32_t sbase = smem_u32p(dsm);
    const int crow = tid >> 1;
    const int cj   = (tid & 1) * 2;
    const int rsw  = (crow >> 1) & 1;

    float acc[4][4][4];
#pragma unroll
    for (int i = 0; i < 4; ++i)
#pragma unroll
        for (int j = 0; j < 4; ++j)
#pragma unroll
            for (int q = 0; q < 4; ++q) acc[i][j][q] = 0.f;

    auto issue = [&](int s) {
        const uint32_t st = sbase + ((s % 3) * STAGE_U32) * 4;
        const size_t ga = (size_t)(m0 + crow) * K2 + (size_t)s * 16;
        const size_t gb = (size_t)(n0 + crow) * K2 + (size_t)s * 16;
#pragma unroll
        for (int c = 0; c < 2; ++c) {
            const int j  = cj + (c ^ rsw);
            const int jp = j ^ (crow & 3);
            const uint32_t d = st + (crow * 16 + jp * 4) * 4;
            cp16(d,                    Ahi + ga + j * 4);
            cp16(d + BUF_U32 * 4,      Alo + ga + j * 4);
            cp16(d + 2 * BUF_U32 * 4,  Bhi + gb + j * 4);
            cp16(d + 3 * BUF_U32 * 4,  Blo + gb + j * 4);
        }
    };

    issue(0); cp_commit();
    issue(1); cp_commit();

    for (int s = 0; s < nst; ++s) {
        if (s < nst - 1) cp_wait1(); else cp_wait0();
        __syncthreads();
        if (s + 2 < nst) { issue(s + 2); cp_commit(); }

        const uint32_t* st   = dsm + (s % 3) * STAGE_U32;
        const uint32_t* pAhi = st;
        const uint32_t* pAlo = st + BUF_U32;
        const uint32_t* pBhi = st + 2 * BUF_U32;
        const uint32_t* pBlo = st + 3 * BUF_U32;

#pragma unroll
        for (int ks = 0; ks < 2; ++ks) {
            const int jw = ks * 8 + 2 * lc;
            uint2 aH0[4], aH1[4], aL0[4], aL1[4], bH[4], bL[4];
#pragma unroll
            for (int mt = 0; mt < 4; ++mt) {
                int r0 = wm * 64 + mt * 16 + lg;
                int sx = (r0 & 3) << 2;
                int o0 = r0 * 16 + (jw ^ sx);
                int o1 = (r0 + 8) * 16 + (jw ^ sx);
                aH0[mt] = *reinterpret_cast<const uint2*>(pAhi + o0);
                aH1[mt] = *reinterpret_cast<const uint2*>(pAhi + o1);
                aL0[mt] = *reinterpret_cast<const uint2*>(pAlo + o0);
                aL1[mt] = *reinterpret_cast<const uint2*>(pAlo + o1);
            }
#pragma unroll
            for (int nt = 0; nt < 4; ++nt) {
                int rb = wn * 32 + nt * 8 + lg;
                int ob = rb * 16 + (jw ^ ((rb & 3) << 2));
                bH[nt] = *reinterpret_cast<const uint2*>(pBhi + ob);
                bL[nt] = *reinterpret_cast<const uint2*>(pBlo + ob);
            }
#pragma unroll
            for (int mt = 0; mt < 4; ++mt) {
                uint32_t ah[4] = {aH0[mt].x, aH1[mt].x, aH0[mt].y, aH1[mt].y};
#pragma unroll
                for (int nt = 0; nt < 4; ++nt) {
                    uint32_t bh[2] = {bH[nt].x, bH[nt].y};
                    mma_bf16(acc[mt][nt], ah, bh);
                }
            }
#pragma unroll
            for (int mt = 0; mt < 4; ++mt) {
                uint32_t ah[4] = {aH0[mt].x, aH1[mt].x, aH0[mt].y, aH1[mt].y};
#pragma unroll
                for (int nt = 0; nt < 4; ++nt) {
                    uint32_t bl[2] = {bL[nt].x, bL[nt].y};
                    mma_bf16(acc[mt][nt], ah, bl);
                }
            }
#pragma unroll
            for (int mt = 0; mt < 4; ++mt) {
                uint32_t al[4] = {aL0[mt].x, aL1[mt].x, aL0[mt].y, aL1[mt].y};
#pragma unroll
                for (int nt = 0; nt < 4; ++nt) {
                    uint32_t bh[2] = {bH[nt].x, bH[nt].y};
                    mma_bf16(acc[mt][nt], al, bh);
                }
            }
        }
    }

#pragma unroll
    for (int mt = 0; mt < 4; ++mt) {
        int r0 = m0 + wm * 64 + mt * 16 + lg;
#pragma unroll
        for (int nt = 0; nt < 4; ++nt) {
            int gc = n0 + wn * 32 + nt * 8 + lc * 2;
            if (gc < N) {
                *reinterpret_cast<float2*>(&C[(size_t)r0 * N + gc]) =
                    make_float2(acc[mt][nt][0], acc[mt][nt][1]);
                *reinterpret_cast<float2*>(&C[(size_t)(r0 + 8) * N + gc]) =
                    make_float2(acc[mt][nt][2], acc[mt][nt][3]);
            }
        }
    }
}

// ---------------- fused conv+silu and dt transform (fast-math) --------------
__global__ void conv_dt_kernel(const float* __restrict__ conv_w,
                               const float* __restrict__ conv_b,
                               const float* __restrict__ dt_bias,
                               const float* __restrict__ A_log)
{
    int idx = blockIdx.x * blockDim.x + threadIdx.x;
    if (idx < LSEQ * CONV_DIM) {
        int c = idx % CONV_DIM;
        int t = idx / CONV_DIM;
        const float4 w = *reinterpret_cast<const float4*>(&conv_w[c * 4]);
        const float* col = g_proj + INTER + c;
        float acc = conv_b[c];
        if (t - 3 >= 0) acc = fmaf(col[(size_t)(t - 3) * PROJ], w.x, acc);
        if (t - 2 >= 0) acc = fmaf(col[(size_t)(t - 2) * PROJ], w.y, acc);
        if (t - 1 >= 0) acc = fmaf(col[(size_t)(t - 1) * PROJ], w.z, acc);
        acc = fmaf(col[(size_t)t * PROJ], w.w, acc);
        g_conv[idx] = fast_silu(acc);
    } else {
        int j = idx - LSEQ * CONV_DIM;
        if (j >= LSEQ * HEADS) return;
        int h = j & (HEADS - 1);
        int t = j >> 6;
        float z = g_proj[(size_t)t * PROJ + INTER + CONV_DIM + h] + dt_bias[h];
        float d = (z > 20.f) ? z : log1pf(__expf(z));
        float A = -__expf(A_log[h]);
        g_dtv[j] = d;
        g_dA[j]  = __expf(d * A);
    }
}

// ---------------- selective scan v3 (measured best, R10 verbatim) ------------
#define TCH 8
#define NCH (LSEQ / TCH)
__global__ __launch_bounds__(128) void scan_kernel(const float* __restrict__ D)
{
    const int h   = blockIdx.x >> 2;
    const int ph  = (blockIdx.x >> 1) & 1;
    const int nh  = blockIdx.x & 1;
    const int tid = threadIdx.x;
    const int pl  = tid >> 2;
    const int q   = tid & 3;
    const int n0  = q * 8;
    const float Dh = D[h];
    float* yout = nh ? g_y2 : g_y;

    __shared__ float sB[2][TCH][32], sC[2][TCH][32], sX[2][TCH][32];
    __shared__ float sDT[2][TCH], sDA[2][TCH];

    const int tl   = tid >> 4;
    const int col2 = tid & 15;

    {
        const float* rowp = g_conv + (size_t)tl * CONV_DIM;
        *reinterpret_cast<float2*>(&sB[0][tl][col2 * 2]) =
            *reinterpret_cast<const float2*>(&rowp[INTER + nh * 32 + col2 * 2]);
        *reinterpret_cast<float2*>(&sC[0][tl][col2 * 2]) =
            *reinterpret_cast<const float2*>(&rowp[INTER + STATE + nh * 32 + col2 * 2]);
        *reinterpret_cast<float2*>(&sX[0][tl][col2 * 2]) =
            *reinterpret_cast<const float2*>(&rowp[h * HEAD_DIM + ph * 32 + col2 * 2]);
        if (tid < TCH)           sDT[0][tid]       = g_dtv[tid * HEADS + h];
        else if (tid < 2 * TCH)  sDA[0][tid - TCH] = g_dA[(tid - TCH) * HEADS + h];
    }
    __syncthreads();

    float s[8];
#pragma unroll
    for (int i = 0; i < 8; ++i) s[i] = 0.f;

    for (int c = 0; c < NCH; ++c) {
        const int buf = c & 1;
        const int t0  = c * TCH;
        const bool more = (c + 1 < NCH);

        float2 nB, nC, nX; float nS = 0.f;
        if (more) {
            const float* rowp = g_conv + (size_t)(t0 + TCH + tl) * CONV_DIM;
            nB = *reinterpret_cast<const float2*>(&rowp[INTER + nh * 32 + col2 * 2]);
            nC = *reinterpret_cast<const float2*>(&rowp[INTER + STATE + nh * 32 + col2 * 2]);
            nX = *reinterpret_cast<const float2*>(&rowp[h * HEAD_DIM + ph * 32 + col2 * 2]);
            if (tid < TCH)           nS = g_dtv[(t0 + TCH + tid) * HEADS + h];
            else if (tid < 2 * TCH)  nS = g_dA[(t0 + TCH + tid - TCH) * HEADS + h];
        }

#pragma unroll
        for (int k = 0; k < TCH; ++k) {
            const float a   = sDA[buf][k];
            const float dtv = sDT[buf][k];
            const float xv  = sX[buf][k][pl];
            const float dtx = dtv * xv;
            float4 b0 = *reinterpret_cast<const float4*>(&sB[buf][k][n0]);
            float4 b1 = *reinterpret_cast<const float4*>(&sB[buf][k][n0 + 4]);
            float4 c0 = *reinterpret_cast<const float4*>(&sC[buf][k][n0]);
            float4 c1 = *reinterpret_cast<const float4*>(&sC[buf][k][n0 + 4]);
            s[0] = fmaf(a, s[0], dtx * b0.x);
            s[1] = fmaf(a, s[1], dtx * b0.y);
            s[2] = fmaf(a, s[2], dtx * b0.z);
            s[3] = fmaf(a, s[3], dtx * b0.w);
            s[4] = fmaf(a, s[4], dtx * b1.x);
            s[5] = fmaf(a, s[5], dtx * b1.y);
            s[6] = fmaf(a, s[6], dtx * b1.z);
            s[7] = fmaf(a, s[7], dtx * b1.w);
            float e0 = fmaf(s[1], c0.y, s[0] * c0.x);
            float e1 = fmaf(s[3], c0.w, s[2] * c0.z);
            float e2 = fmaf(s[5], c1.y, s[4] * c1.x);
            float e3 = fmaf(s[7], c1.w, s[6] * c1.z);
            float accv = (e0 + e1) + (e2 + e3);
            accv += __shfl_xor_sync(0xffffffffu, accv, 1);
            accv += __shfl_xor_sync(0xffffffffu, accv, 2);
            if (q == 0) {
                float o = accv + (nh == 0 ? Dh * xv : 0.f);
                yout[(size_t)(t0 + k) * INTER + h * HEAD_DIM + ph * 32 + pl] = o;
            }
        }

        if (more) {
            const int nb = buf ^ 1;
            *reinterpret_cast<float2*>(&sB[nb][tl][col2 * 2]) = nB;
            *reinterpret_cast<float2*>(&sC[nb][tl][col2 * 2]) = nC;
            *reinterpret_cast<float2*>(&sX[nb][tl][col2 * 2]) = nX;
            if (tid < TCH)           sDT[nb][tid]       = nS;
            else if (tid < 2 * TCH)  sDA[nb][tid - TCH] = nS;
        }
        __syncthreads();
    }
}

// ---------------- RMSNorm * silu(gate) -> bf16 hi/lo (fast-math) -------------
__global__ __launch_bounds__(256) void norm_gate_cvt(const float* __restrict__ nw)
{
    const int t = blockIdx.x;
    const float* y1 = g_y  + (size_t)t * INTER;
    const float* y2 = g_y2 + (size_t)t * INTER;
    const float* gp = g_proj + (size_t)t * PROJ;
    __shared__ float red[256];
    float ss = 0.f;
    for (int c = threadIdx.x; c < INTER; c += 256) {
        float v = y1[c] + y2[c];
        ss = fmaf(v, v, ss);
    }
    red[threadIdx.x] = ss;
    __syncthreads();
    for (int off = 128; off > 0; off >>= 1) {
        if (threadIdx.x < off) red[threadIdx.x] += red[threadIdx.x + off];
        __syncthreads();
    }
    const float r = rsqrtf(red[0] / (float)INTER + 1e-6f);

    const int K2 = INTER / 2;
    for (int J = threadIdx.x; J < K2; J += 256) {
        int g = J >> 3, p = J & 7;
        int jl = (g << 3) + (p >> 1) + ((p & 1) << 2);
        int c0 = 2 * jl;
        float ga = gp[c0], gb = gp[c0 + 1];
        float v0 = (y1[c0] + y2[c0]) * r * nw[c0] * fast_silu(ga);
        float v1 = (y1[c0 + 1] + y2[c0 + 1]) * r * nw[c0 + 1] * fast_silu(gb);
        uint32_t h, l;
        split_pack(v0, v1, h, l);
        g_yn_hi[(size_t)t * K2 + J] = h;
        g_yn_lo[(size_t)t * K2 + J] = l;
    }
}

// ---------------- launch ------------------------------------------------------
extern "C" void kernel_launch(void* const* d_in, const int* in_sizes, int n_in,
                              void* d_out, int out_size)
{
    const float* hidden     = (const float*)d_in[0];
    const float* in_proj_w  = (const float*)d_in[1];
    const float* conv_w     = (const float*)d_in[2];
    const float* conv_b     = (const float*)d_in[3];
    const float* dt_bias    = (const float*)d_in[4];
    const float* A_log      = (const float*)d_in[5];
    const float* Dv         = (const float*)d_in[6];
    const float* norm_w     = (const float*)d_in[7];
    const float* out_proj_w = (const float*)d_in[8];
    float* out = (float*)d_out;

    float* p_proj = nullptr;
    cudaGetSymbolAddress((void**)&p_proj, g_proj);
    uint32_t *p_hhi, *p_hlo, *p_w1hi, *p_w1lo, *p_w2hi, *p_w2lo, *p_ynhi, *p_ynlo;
    cudaGetSymbolAddress((void**)&p_hhi, g_h_hi);
    cudaGetSymbolAddress((void**)&p_hlo, g_h_lo);
    cudaGetSymbolAddress((void**)&p_w1hi, g_w1_hi);
    cudaGetSymbolAddress((void**)&p_w1lo, g_w1_lo);
    cudaGetSymbolAddress((void**)&p_w2hi, g_w2_hi);
    cudaGetSymbolAddress((void**)&p_w2lo, g_w2_lo);
    cudaGetSymbolAddress((void**)&p_ynhi, g_yn_hi);
    cudaGetSymbolAddress((void**)&p_ynlo, g_yn_lo);

    cudaFuncSetAttribute(gemm_bf3, cudaFuncAttributeMaxDynamicSharedMemorySize, GEMM_SMEM_BYTES);

    // operand converts needed before GEMM1
    cvt_split<<<dim3(HIDDEN / 2 / 256, LSEQ), 256>>>(hidden, p_hhi, p_hlo, LSEQ, HIDDEN);
    cvt_split<<<dim3(HIDDEN / 2 / 256, W1_RPAD), 256>>>(in_proj_w, p_w1hi, p_w1lo, PROJ, HIDDEN);

    // GEMM1: proj = hidden @ in_proj_w^T : M=2048, N=8384 (pad 8448), K=2048
    gemm_bf3<<<dim3(W1_RPAD / BN, LSEQ / BM), 256, GEMM_SMEM_BYTES>>>(
        p_hhi, p_hlo, p_w1hi, p_w1lo, p_proj, LSEQ, PROJ, HIDDEN);

    // fork: w2 conversion overlaps with latency-bound scan branch (R14 pattern)
    cudaStream_t s1;
    cudaStreamCreateWithFlags(&s1, cudaStreamNonBlocking);
    cudaEvent_t evA, evB;
    cudaEventCreateWithFlags(&evA, cudaEventDisableTiming);
    cudaEventCreateWithFlags(&evB, cudaEventDisableTiming);

    cudaEventRecord(evA, 0);
    cudaStreamWaitEvent(s1, evA, 0);
    cvt_split<<<dim3(INTER / 2 / 256, HIDDEN), 256, 0, s1>>>(out_proj_w, p_w2hi, p_w2lo, HIDDEN, INTER);
    cudaEventRecord(evB, s1);

    // scan branch (legacy stream)
    {
        int total = LSEQ * (CONV_DIM + HEADS);
        conv_dt_kernel<<<(total + 255) / 256, 256>>>(conv_w, conv_b, dt_bias, A_log);
    }
    scan_kernel<<<HEADS * 4, 128>>>(Dv);
    norm_gate_cvt<<<LSEQ, 256>>>(norm_w);

    // join before GEMM2 (needs w2 converts + yn)
    cudaStreamWaitEvent(0, evB, 0);

    // GEMM2: out = y' @ out_proj_w^T : M=2048, N=2048, K=4096
    gemm_bf3<<<dim3(HIDDEN / BN, LSEQ / BM), 256, GEMM_SMEM_BYTES>>>(
        p_ynhi, p_ynlo, p_w2hi, p_w2lo, out, LSEQ, HIDDEN, INTER);

    cudaEventDestroy(evA);
    cudaEventDestroy(evB);
    cudaStreamDestroy(s1);
}

// round 17
// speedup vs baseline: 1.0578x; 1.0003x over previous
#include <cuda_runtime.h>
#include <cuda_bf16.h>
#include <cstdint>
#include <math.h>

#define LSEQ     2048
#define HIDDEN   2048
#define INTER    4096
#define HEADS    64
#define HEAD_DIM 64
#define STATE    64
#define KCONV    4
#define CONV_DIM (INTER + 2 * STATE)            // 4224
#define PROJ     (INTER + CONV_DIM + HEADS)     // 8384
#define W1_RPAD  8448                           // PROJ padded to 128

// ---------------- scratch ------------------------------------------------
__device__ float g_proj[(size_t)LSEQ * PROJ];
__device__ float g_conv[(size_t)LSEQ * CONV_DIM];
__device__ float g_y[(size_t)LSEQ * INTER];      // scan partial (n 0..31)
__device__ float g_y2[(size_t)LSEQ * INTER];     // scan partial (n 32..63)
__device__ float g_dtv[LSEQ * HEADS];
__device__ float g_dA[LSEQ * HEADS];
// bf16 split operands (u32 = packed bf16 pair, k-permuted layout)
__device__ uint32_t g_h_hi[(size_t)LSEQ * (HIDDEN / 2)];
__device__ uint32_t g_h_lo[(size_t)LSEQ * (HIDDEN / 2)];
__device__ uint32_t g_w1_hi[(size_t)W1_RPAD * (HIDDEN / 2)];
__device__ uint32_t g_w1_lo[(size_t)W1_RPAD * (HIDDEN / 2)];
__device__ uint32_t g_w2_hi[(size_t)HIDDEN * (INTER / 2)];
__device__ uint32_t g_w2_lo[(size_t)HIDDEN * (INTER / 2)];
__device__ uint32_t g_yn_hi[(size_t)LSEQ * (INTER / 2)];
__device__ uint32_t g_yn_lo[(size_t)LSEQ * (INTER / 2)];

// ---------------- helpers --------------------------------------------------
__device__ __forceinline__ float fast_silu(float x) {
    return __fdividef(x, 1.f + __expf(-x));
}

__device__ __forceinline__ void split_pack(float x0, float x1, uint32_t& hi, uint32_t& lo) {
    __nv_bfloat16 h0 = __float2bfloat16(x0);
    __nv_bfloat16 h1 = __float2bfloat16(x1);
    __nv_bfloat16 l0 = __float2bfloat16(x0 - __bfloat162float(h0));
    __nv_bfloat16 l1 = __float2bfloat16(x1 - __bfloat162float(h1));
    hi = (uint32_t)__bfloat16_as_ushort(h0) | ((uint32_t)__bfloat16_as_ushort(h1) << 16);
    lo = (uint32_t)__bfloat16_as_ushort(l0) | ((uint32_t)__bfloat16_as_ushort(l1) << 16);
}

__device__ __forceinline__ void mma_bf16(float* d, const uint32_t* a, const uint32_t* b) {
    asm volatile(
        "mma.sync.aligned.m16n8k16.row.col.f32.bf16.bf16.f32 "
        "{%0,%1,%2,%3}, {%4,%5,%6,%7}, {%8,%9}, {%0,%1,%2,%3};"
        : "+f"(d[0]), "+f"(d[1]), "+f"(d[2]), "+f"(d[3])
        : "r"(a[0]), "r"(a[1]), "r"(a[2]), "r"(a[3]), "r"(b[0]), "r"(b[1]));
}

__device__ __forceinline__ uint32_t smem_u32p(const void* p) {
    uint32_t a;
    asm("{ .reg .u64 t; cvta.to.shared.u64 t, %1; cvt.u32.u64 %0, t; }" : "=r"(a) : "l"(p));
    return a;
}
__device__ __forceinline__ void cp16(uint32_t dst, const void* src) {
    asm volatile("cp.async.cg.shared.global [%0], [%1], 16;" :: "r"(dst), "l"(src));
}
__device__ __forceinline__ void cp_commit() { asm volatile("cp.async.commit_group;"); }
__device__ __forceinline__ void cp_wait1()  { asm volatile("cp.async.wait_group 1;" ::: "memory"); }
__device__ __forceinline__ void cp_wait0()  { asm volatile("cp.async.wait_group 0;" ::: "memory"); }

// ---------------- convert f32 -> permuted bf16 hi/lo pairs (R5 layout) -----
__global__ void cvt_split(const float* __restrict__ in, uint32_t* __restrict__ hi,
                          uint32_t* __restrict__ lo, int R, int K)
{
    const int K2 = K >> 1;
    int jj  = blockIdx.x * blockDim.x + threadIdx.x;
    int row = blockIdx.y;
    if (jj >= K2) return;
    int g = jj >> 3, p = jj & 7;
    int jl = (g << 3) + (p >> 1) + ((p & 1) << 2);
    float a0 = 0.f, a1 = 0.f;
    if (row < R) {
        a0 = in[(size_t)row * K + 2 * jl];
        a1 = in[(size_t)row * K + 2 * jl + 1];
    }
    uint32_t h, l;
    split_pack(a0, a1, h, l);
    hi[(size_t)row * K2 + jj] = h;
    lo[(size_t)row * K2 + jj] = l;
}

// ---------------- bf16x3 GEMM (R10 measured best, unchanged) ----------------
#define BM 128
#define BN 128
#define BKE 32
#define BUF_U32 (BM * 16)              // 2048
#define STAGE_U32 (4 * BUF_U32)        // 8192
#define GEMM_SMEM_BYTES (3 * STAGE_U32 * 4)   // 98304

__global__ __launch_bounds__(256, 2) void gemm_bf3(
    const uint32_t* __restrict__ Ahi, const uint32_t* __restrict__ Alo,
    const uint32_t* __restrict__ Bhi, const uint32_t* __restrict__ Blo,
    float* __restrict__ C, int M, int N, int K)
{
    extern __shared__ uint32_t dsm[];
    const int K2  = K >> 1;
    const int nst = K / BKE;
    const int tid  = threadIdx.x;
    const int wid  = tid >> 5;
    const int lane = tid & 31;
    const int wm   = wid & 1;
    const int wn   = wid >> 1;
    const int m0   = blockIdx.y * BM;
    const int n0   = blockIdx.x * BN;
    const int lg   = lane >> 2;
    const int lc   = lane & 3;

    const uint32_t sbase = smem_u32p(dsm);
    const int crow = tid >> 1;
    const int cj   = (tid & 1) * 2;
    const int rsw  = (crow >> 1) & 1;

    float acc[4][4][4];
#pragma unroll
    for (int i = 0; i < 4; ++i)
#pragma unroll
        for (int j = 0; j < 4; ++j)
#pragma unroll
            for (int q = 0; q < 4; ++q) acc[i][j][q] = 0.f;

    auto issue = [&](int s) {
        const uint32_t st = sbase + ((s % 3) * STAGE_U32) * 4;
        const size_t ga = (size_t)(m0 + crow) * K2 + (size_t)s * 16;
        const size_t gb = (size_t)(n0 + crow) * K2 + (size_t)s * 16;
#pragma unroll
        for (int c = 0; c < 2; ++c) {
            const int j  = cj + (c ^ rsw);
            const int jp = j ^ (crow & 3);
            const uint32_t d = st + (crow * 16 + jp * 4) * 4;
            cp16(d,                    Ahi + ga + j * 4);
            cp16(d + BUF_U32 * 4,      Alo + ga + j * 4);
            cp16(d + 2 * BUF_U32 * 4,  Bhi + gb + j * 4);
            cp16(d + 3 * BUF_U32 * 4,  Blo + gb + j * 4);
        }
    };

    issue(0); cp_commit();
    issue(1); cp_commit();

    for (int s = 0; s < nst; ++s) {
        if (s < nst - 1) cp_wait1(); else cp_wait0();
        __syncthreads();
        if (s + 2 < nst) { issue(s + 2); cp_commit(); }

        const uint32_t* st   = dsm + (s % 3) * STAGE_U32;
        const uint32_t* pAhi = st;
        const uint32_t* pAlo = st + BUF_U32;
        const uint32_t* pBhi = st + 2 * BUF_U32;
        const uint32_t* pBlo = st + 3 * BUF_U32;

#pragma unroll
        for (int ks = 0; ks < 2; ++ks) {
            const int jw = ks * 8 + 2 * lc;
            uint2 aH0[4], aH1[4], aL0[4], aL1[4], bH[4], bL[4];
#pragma unroll
            for (int mt = 0; mt < 4; ++mt) {
                int r0 = wm * 64 + mt * 16 + lg;
                int sx = (r0 & 3) << 2;
                int o0 = r0 * 16 + (jw ^ sx);
                int o1 = (r0 + 8) * 16 + (jw ^ sx);
                aH0[mt] = *reinterpret_cast<const uint2*>(pAhi + o0);
                aH1[mt] = *reinterpret_cast<const uint2*>(pAhi + o1);
                aL0[mt] = *reinterpret_cast<const uint2*>(pAlo + o0);
                aL1[mt] = *reinterpret_cast<const uint2*>(pAlo + o1);
            }
#pragma unroll
            for (int nt = 0; nt < 4; ++nt) {
                int rb = wn * 32 + nt * 8 + lg;
                int ob = rb * 16 + (jw ^ ((rb & 3) << 2));
                bH[nt] = *reinterpret_cast<const uint2*>(pBhi + ob);
                bL[nt] = *reinterpret_cast<const uint2*>(pBlo + ob);
            }
#pragma unroll
            for (int mt = 0; mt < 4; ++mt) {
                uint32_t ah[4] = {aH0[mt].x, aH1[mt].x, aH0[mt].y, aH1[mt].y};
#pragma unroll
                for (int nt = 0; nt < 4; ++nt) {
                    uint32_t bh[2] = {bH[nt].x, bH[nt].y};
                    mma_bf16(acc[mt][nt], ah, bh);
                }
            }
#pragma unroll
            for (int mt = 0; mt < 4; ++mt) {
                uint32_t ah[4] = {aH0[mt].x, aH1[mt].x, aH0[mt].y, aH1[mt].y};
#pragma unroll
                for (int nt = 0; nt < 4; ++nt) {
                    uint32_t bl[2] = {bL[nt].x, bL[nt].y};
                    mma_bf16(acc[mt][nt], ah, bl);
                }
            }
#pragma unroll
            for (int mt = 0; mt < 4; ++mt) {
                uint32_t al[4] = {aL0[mt].x, aL1[mt].x, aL0[mt].y, aL1[mt].y};
#pragma unroll
                for (int nt = 0; nt < 4; ++nt) {
                    uint32_t bh[2] = {bH[nt].x, bH[nt].y};
                    mma_bf16(acc[mt][nt], al, bh);
                }
            }
        }
    }

#pragma unroll
    for (int mt = 0; mt < 4; ++mt) {
        int r0 = m0 + wm * 64 + mt * 16 + lg;
#pragma unroll
        for (int nt = 0; nt < 4; ++nt) {
            int gc = n0 + wn * 32 + nt * 8 + lc * 2;
            if (gc < N) {
                *reinterpret_cast<float2*>(&C[(size_t)r0 * N + gc]) =
                    make_float2(acc[mt][nt][0], acc[mt][nt][1]);
                *reinterpret_cast<float2*>(&C[(size_t)(r0 + 8) * N + gc]) =
                    make_float2(acc[mt][nt][2], acc[mt][nt][3]);
            }
        }
    }
}

// ---------------- fused conv+silu and dt transform (fast-math) --------------
__global__ void conv_dt_kernel(const float* __restrict__ conv_w,
                               const float* __restrict__ conv_b,
                               const float* __restrict__ dt_bias,
                               const float* __restrict__ A_log)
{
    int idx = blockIdx.x * blockDim.x + threadIdx.x;
    if (idx < LSEQ * CONV_DIM) {
        int c = idx % CONV_DIM;
        int t = idx / CONV_DIM;
        const float4 w = *reinterpret_cast<const float4*>(&conv_w[c * 4]);
        const float* col = g_proj + INTER + c;
        float acc = conv_b[c];
        if (t - 3 >= 0) acc = fmaf(col[(size_t)(t - 3) * PROJ], w.x, acc);
        if (t - 2 >= 0) acc = fmaf(col[(size_t)(t - 2) * PROJ], w.y, acc);
        if (t - 1 >= 0) acc = fmaf(col[(size_t)(t - 1) * PROJ], w.z, acc);
        acc = fmaf(col[(size_t)t * PROJ], w.w, acc);
        g_conv[idx] = fast_silu(acc);
    } else {
        int j = idx - LSEQ * CONV_DIM;
        if (j >= LSEQ * HEADS) return;
        int h = j & (HEADS - 1);
        int t = j >> 6;
        float z = g_proj[(size_t)t * PROJ + INTER + CONV_DIM + h] + dt_bias[h];
        float d = (z > 20.f) ? z : log1pf(__expf(z));
        float A = -__expf(A_log[h]);
        g_dtv[j] = d;
        g_dA[j]  = __expf(d * A);
    }
}

// ---------------- selective scan v3 (measured best, R10 verbatim) ------------
#define TCH 8
#define NCH (LSEQ / TCH)
__global__ __launch_bounds__(128) void scan_kernel(const float* __restrict__ D)
{
    const int h   = blockIdx.x >> 2;
    const int ph  = (blockIdx.x >> 1) & 1;
    const int nh  = blockIdx.x & 1;
    const int tid = threadIdx.x;
    const int pl  = tid >> 2;
    const int q   = tid & 3;
    const int n0  = q * 8;
    const float Dh = D[h];
    float* yout = nh ? g_y2 : g_y;

    __shared__ float sB[2][TCH][32], sC[2][TCH][32], sX[2][TCH][32];
    __shared__ float sDT[2][TCH], sDA[2][TCH];

    const int tl   = tid >> 4;
    const int col2 = tid & 15;

    {
        const float* rowp = g_conv + (size_t)tl * CONV_DIM;
        *reinterpret_cast<float2*>(&sB[0][tl][col2 * 2]) =
            *reinterpret_cast<const float2*>(&rowp[INTER + nh * 32 + col2 * 2]);
        *reinterpret_cast<float2*>(&sC[0][tl][col2 * 2]) =
            *reinterpret_cast<const float2*>(&rowp[INTER + STATE + nh * 32 + col2 * 2]);
        *reinterpret_cast<float2*>(&sX[0][tl][col2 * 2]) =
            *reinterpret_cast<const float2*>(&rowp[h * HEAD_DIM + ph * 32 + col2 * 2]);
        if (tid < TCH)           sDT[0][tid]       = g_dtv[tid * HEADS + h];
        else if (tid < 2 * TCH)  sDA[0][tid - TCH] = g_dA[(tid - TCH) * HEADS + h];
    }
    __syncthreads();

    float s[8];
#pragma unroll
    for (int i = 0; i < 8; ++i) s[i] = 0.f;

    for (int c = 0; c < NCH; ++c) {
        const int buf = c & 1;
        const int t0  = c * TCH;
        const bool more = (c + 1 < NCH);

        float2 nB, nC, nX; float nS = 0.f;
        if (more) {
            const float* rowp = g_conv + (size_t)(t0 + TCH + tl) * CONV_DIM;
            nB = *reinterpret_cast<const float2*>(&rowp[INTER + nh * 32 + col2 * 2]);
            nC = *reinterpret_cast<const float2*>(&rowp[INTER + STATE + nh * 32 + col2 * 2]);
            nX = *reinterpret_cast<const float2*>(&rowp[h * HEAD_DIM + ph * 32 + col2 * 2]);
            if (tid < TCH)           nS = g_dtv[(t0 + TCH + tid) * HEADS + h];
            else if (tid < 2 * TCH)  nS = g_dA[(t0 + TCH + tid - TCH) * HEADS + h];
        }

#pragma unroll
        for (int k = 0; k < TCH; ++k) {
            const float a   = sDA[buf][k];
            const float dtv = sDT[buf][k];
            const float xv  = sX[buf][k][pl];
            const float dtx = dtv * xv;
            float4 b0 = *reinterpret_cast<const float4*>(&sB[buf][k][n0]);
            float4 b1 = *reinterpret_cast<const float4*>(&sB[buf][k][n0 + 4]);
            float4 c0 = *reinterpret_cast<const float4*>(&sC[buf][k][n0]);
            float4 c1 = *reinterpret_cast<const float4*>(&sC[buf][k][n0 + 4]);
            s[0] = fmaf(a, s[0], dtx * b0.x);
            s[1] = fmaf(a, s[1], dtx * b0.y);
            s[2] = fmaf(a, s[2], dtx * b0.z);
            s[3] = fmaf(a, s[3], dtx * b0.w);
            s[4] = fmaf(a, s[4], dtx * b1.x);
            s[5] = fmaf(a, s[5], dtx * b1.y);
            s[6] = fmaf(a, s[6], dtx * b1.z);
            s[7] = fmaf(a, s[7], dtx * b1.w);
            float e0 = fmaf(s[1], c0.y, s[0] * c0.x);
            float e1 = fmaf(s[3], c0.w, s[2] * c0.z);
            float e2 = fmaf(s[5], c1.y, s[4] * c1.x);
            float e3 = fmaf(s[7], c1.w, s[6] * c1.z);
            float accv = (e0 + e1) + (e2 + e3);
            accv += __shfl_xor_sync(0xffffffffu, accv, 1);
            accv += __shfl_xor_sync(0xffffffffu, accv, 2);
            if (q == 0) {
                float o = accv + (nh == 0 ? Dh * xv : 0.f);
                yout[(size_t)(t0 + k) * INTER + h * HEAD_DIM + ph * 32 + pl] = o;
            }
        }

        if (more) {
            const int nb = buf ^ 1;
            *reinterpret_cast<float2*>(&sB[nb][tl][col2 * 2]) = nB;
            *reinterpret_cast<float2*>(&sC[nb][tl][col2 * 2]) = nC;
            *reinterpret_cast<float2*>(&sX[nb][tl][col2 * 2]) = nX;
            if (tid < TCH)           sDT[nb][tid]       = nS;
            else if (tid < 2 * TCH)  sDA[nb][tid - TCH] = nS;
        }
        __syncthreads();
    }
}

// ---------------- RMSNorm * silu(gate) -> bf16 hi/lo (fast-math) -------------
__global__ __launch_bounds__(256) void norm_gate_cvt(const float* __restrict__ nw)
{
    const int t = blockIdx.x;
    const float* y1 = g_y  + (size_t)t * INTER;
    const float* y2 = g_y2 + (size_t)t * INTER;
    const float* gp = g_proj + (size_t)t * PROJ;
    __shared__ float red[256];
    float ss = 0.f;
    for (int c = threadIdx.x; c < INTER; c += 256) {
        float v = y1[c] + y2[c];
        ss = fmaf(v, v, ss);
    }
    red[threadIdx.x] = ss;
    __syncthreads();
    for (int off = 128; off > 0; off >>= 1) {
        if (threadIdx.x < off) red[threadIdx.x] += red[threadIdx.x + off];
        __syncthreads();
    }
    const float r = rsqrtf(red[0] / (float)INTER + 1e-6f);

    const int K2 = INTER / 2;
    for (int J = threadIdx.x; J < K2; J += 256) {
        int g = J >> 3, p = J & 7;
        int jl = (g << 3) + (p >> 1) + ((p & 1) << 2);
        int c0 = 2 * jl;
        float ga = gp[c0], gb = gp[c0 + 1];
        float v0 = (y1[c0] + y2[c0]) * r * nw[c0] * fast_silu(ga);
        float v1 = (y1[c0 + 1] + y2[c0 + 1]) * r * nw[c0 + 1] * fast_silu(gb);
        uint32_t h, l;
        split_pack(v0, v1, h, l);
        g_yn_hi[(size_t)t * K2 + J] = h;
        g_yn_lo[(size_t)t * K2 + J] = l;
    }
}

// ---------------- launch ------------------------------------------------------
extern "C" void kernel_launch(void* const* d_in, const int* in_sizes, int n_in,
                              void* d_out, int out_size)
{
    const float* hidden     = (const float*)d_in[0];
    const float* in_proj_w  = (const float*)d_in[1];
    const float* conv_w     = (const float*)d_in[2];
    const float* conv_b     = (const float*)d_in[3];
    const float* dt_bias    = (const float*)d_in[4];
    const float* A_log      = (const float*)d_in[5];
    const float* Dv         = (const float*)d_in[6];
    const float* norm_w     = (const float*)d_in[7];
    const float* out_proj_w = (const float*)d_in[8];
    float* out = (float*)d_out;

    float* p_proj = nullptr;
    cudaGetSymbolAddress((void**)&p_proj, g_proj);
    uint32_t *p_hhi, *p_hlo, *p_w1hi, *p_w1lo, *p_w2hi, *p_w2lo, *p_ynhi, *p_ynlo;
    cudaGetSymbolAddress((void**)&p_hhi, g_h_hi);
    cudaGetSymbolAddress((void**)&p_hlo, g_h_lo);
    cudaGetSymbolAddress((void**)&p_w1hi, g_w1_hi);
    cudaGetSymbolAddress((void**)&p_w1lo, g_w1_lo);
    cudaGetSymbolAddress((void**)&p_w2hi, g_w2_hi);
    cudaGetSymbolAddress((void**)&p_w2lo, g_w2_lo);
    cudaGetSymbolAddress((void**)&p_ynhi, g_yn_hi);
    cudaGetSymbolAddress((void**)&p_ynlo, g_yn_lo);

    cudaFuncSetAttribute(gemm_bf3, cudaFuncAttributeMaxDynamicSharedMemorySize, GEMM_SMEM_BYTES);

    // fork: all three prologue converts run concurrently.
    //   legacy : w1 cvt (longest, 34us) -> GEMM1 ...
    //   s1     : w2 cvt (joined before GEMM2)
    //   s2     : hidden cvt (joined before GEMM1)
    cudaStream_t s1, s2;
    cudaStreamCreateWithFlags(&s1, cudaStreamNonBlocking);
    cudaStreamCreateWithFlags(&s2, cudaStreamNonBlocking);
    cudaEvent_t evA, evB, evC;
    cudaEventCreateWithFlags(&evA, cudaEventDisableTiming);
    cudaEventCreateWithFlags(&evB, cudaEventDisableTiming);
    cudaEventCreateWithFlags(&evC, cudaEventDisableTiming);

    cudaEventRecord(evA, 0);
    cudaStreamWaitEvent(s1, evA, 0);
    cudaStreamWaitEvent(s2, evA, 0);

    cvt_split<<<dim3(INTER / 2 / 256, HIDDEN), 256, 0, s1>>>(out_proj_w, p_w2hi, p_w2lo, HIDDEN, INTER);
    cudaEventRecord(evB, s1);

    cvt_split<<<dim3(HIDDEN / 2 / 256, LSEQ), 256, 0, s2>>>(hidden, p_hhi, p_hlo, LSEQ, HIDDEN);
    cudaEventRecord(evC, s2);

    cvt_split<<<dim3(HIDDEN / 2 / 256, W1_RPAD), 256>>>(in_proj_w, p_w1hi, p_w1lo, PROJ, HIDDEN);

    // GEMM1 needs hidden cvt (s2) + w1 cvt (legacy)
    cudaStreamWaitEvent(0, evC, 0);

    // GEMM1: proj = hidden @ in_proj_w^T : M=2048, N=8384 (pad 8448), K=2048
    gemm_bf3<<<dim3(W1_RPAD / BN, LSEQ / BM), 256, GEMM_SMEM_BYTES>>>(
        p_hhi, p_hlo, p_w1hi, p_w1lo, p_proj, LSEQ, PROJ, HIDDEN);

    // scan branch (legacy stream)
    {
        int total = LSEQ * (CONV_DIM + HEADS);
        conv_dt_kernel<<<(total + 255) / 256, 256>>>(conv_w, conv_b, dt_bias, A_log);
    }
    scan_kernel<<<HEADS * 4, 128>>>(Dv);
    norm_gate_cvt<<<LSEQ, 256>>>(norm_w);

    // join before GEMM2 (needs w2 converts + yn)
    cudaStreamWaitEvent(0, evB, 0);

    // GEMM2: out = y' @ out_proj_w^T : M=2048, N=2048, K=4096
    gemm_bf3<<<dim3(HIDDEN / BN, LSEQ / BM), 256, GEMM_SMEM_BYTES>>>(
        p_ynhi, p_ynlo, p_w2hi, p_w2lo, out, LSEQ, HIDDEN, INTER);

    cudaEventDestroy(evA);
    cudaEventDestroy(evB);
    cudaEventDestroy(evC);
    cudaStreamDestroy(s1);
    cudaStreamDestroy(s2);
}